// round 3
// baseline (speedup 1.0000x reference)
#include <cuda_runtime.h>
#include <math.h>

#define T_SEQ 2048
#define C_DIM 1024
#define HEADS 16
#define KV_HEADS 4
#define HDIM 64
#define KV_DIM 512
#define WINDOW_SZ 512

// Scratch (no cudaMalloc allowed)
__device__ float g_q[T_SEQ * C_DIM];    // 8 MB
__device__ float g_kv[T_SEQ * KV_DIM];  // 4 MB  (K: cols 0..255, V: cols 256..511)
__device__ float g_y[T_SEQ * C_DIM];    // 8 MB

// ---------------------------------------------------------------------------
// GEMM: C[M,N] = A[M,K] * B[N,K]^T   (both operands K-major / row-major)
// 128x128 tile, BK=8, 256 threads, 8x8 per-thread microtile.
// ---------------------------------------------------------------------------
#define GBM 128
#define GBN 128
#define GBK 8
#define GST 132   // padded stride: conflict-free transpose stores + aligned float4 reads

__global__ __launch_bounds__(256, 2)
void gemm_tn(const float* __restrict__ A, const float* __restrict__ B,
             float* __restrict__ C, int M, int N, int K)
{
    __shared__ float As[GBK * GST];
    __shared__ float Bs[GBK * GST];
    const int tid = threadIdx.x;
    const int tx = tid & 15, ty = tid >> 4;
    const int m0 = blockIdx.y * GBM, n0 = blockIdx.x * GBN;
    const int lrow = tid >> 1, lcol = (tid & 1) * 4;

    const float* Ap = A + (size_t)(m0 + lrow) * K + lcol;
    const float* Bp = B + (size_t)(n0 + lrow) * K + lcol;

    float acc[8][8];
#pragma unroll
    for (int i = 0; i < 8; i++)
#pragma unroll
        for (int j = 0; j < 8; j++) acc[i][j] = 0.f;

    for (int k0 = 0; k0 < K; k0 += GBK) {
        float4 av = *reinterpret_cast<const float4*>(Ap + k0);
        float4 bv = *reinterpret_cast<const float4*>(Bp + k0);
        As[(lcol + 0) * GST + lrow] = av.x;
        As[(lcol + 1) * GST + lrow] = av.y;
        As[(lcol + 2) * GST + lrow] = av.z;
        As[(lcol + 3) * GST + lrow] = av.w;
        Bs[(lcol + 0) * GST + lrow] = bv.x;
        Bs[(lcol + 1) * GST + lrow] = bv.y;
        Bs[(lcol + 2) * GST + lrow] = bv.z;
        Bs[(lcol + 3) * GST + lrow] = bv.w;
        __syncthreads();
#pragma unroll
        for (int kk = 0; kk < GBK; kk++) {
            float a[8], b[8];
            float4 t0 = *reinterpret_cast<const float4*>(&As[kk * GST + 4 * ty]);
            float4 t1 = *reinterpret_cast<const float4*>(&As[kk * GST + 4 * ty + 64]);
            float4 t2 = *reinterpret_cast<const float4*>(&Bs[kk * GST + 4 * tx]);
            float4 t3 = *reinterpret_cast<const float4*>(&Bs[kk * GST + 4 * tx + 64]);
            a[0] = t0.x; a[1] = t0.y; a[2] = t0.z; a[3] = t0.w;
            a[4] = t1.x; a[5] = t1.y; a[6] = t1.z; a[7] = t1.w;
            b[0] = t2.x; b[1] = t2.y; b[2] = t2.z; b[3] = t2.w;
            b[4] = t3.x; b[5] = t3.y; b[6] = t3.z; b[7] = t3.w;
#pragma unroll
            for (int i = 0; i < 8; i++)
#pragma unroll
                for (int j = 0; j < 8; j++) acc[i][j] += a[i] * b[j];
        }
        __syncthreads();
    }

#pragma unroll
    for (int i = 0; i < 8; i++) {
        int r = m0 + 4 * ty + (i & 3) + ((i >= 4) ? 64 : 0);
        float4 w0 = make_float4(acc[i][0], acc[i][1], acc[i][2], acc[i][3]);
        float4 w1 = make_float4(acc[i][4], acc[i][5], acc[i][6], acc[i][7]);
        *reinterpret_cast<float4*>(&C[(size_t)r * N + n0 + 4 * tx]) = w0;
        *reinterpret_cast<float4*>(&C[(size_t)r * N + n0 + 64 + 4 * tx]) = w1;
    }
}

// ---------------------------------------------------------------------------
// QK L2-normalize + RoPE. One warp per (t, head). Heads 0..15 -> Q, 16..19 -> K.
// Lane holds pair (lane, lane+32): theta = 10000^(-lane/32).
// ---------------------------------------------------------------------------
__global__ void norm_rope_kernel(float* __restrict__ q, float* __restrict__ kvbuf)
{
    const int t = blockIdx.x;
    const int h = blockIdx.y;
    const int lane = threadIdx.x;
    float* base = (h < HEADS)
        ? q + (size_t)t * C_DIM + h * HDIM
        : kvbuf + (size_t)t * KV_DIM + (h - HEADS) * HDIM;

    float a = base[lane];
    float b = base[lane + 32];
    float ss = a * a + b * b;
#pragma unroll
    for (int off = 16; off > 0; off >>= 1)
        ss += __shfl_xor_sync(0xffffffffu, ss, off);
    float inv = 1.f / (sqrtf(ss) + 1e-6f);

    float theta = powf(10000.f, -(float)lane * (1.f / 32.f));
    float ang = (float)t * theta;
    float sv, cv;
    sincosf(ang, &sv, &cv);

    base[lane]      = (a * cv - b * sv) * inv;
    base[lane + 32] = (b * cv + a * sv) * inv;
}

// ---------------------------------------------------------------------------
// Windowed flash attention. 64 q-rows per block, 64-key tiles, 256 threads,
// 4x4 microtile (thread (ty,tx): rows {ty+16i}, cols {tx+16j}).
// Smem: Qt/Kt XOR-swizzled transposed tiles; Ps overlays Kt buffer; 48KB total.
// ---------------------------------------------------------------------------
__global__ __launch_bounds__(256)
void attn_kernel(const float* __restrict__ q, const float* __restrict__ kv,
                 float* __restrict__ y)
{
    __shared__ float Qt[64 * 64];  // [kk][r], addr = kk*64 + (r ^ (kk&31))
    __shared__ float KP[64 * 64];  // Kt: [kk][c] swizzled; later Ps: [r][k] swizzled
    __shared__ float Vs[64 * 64];  // [k][c] plain

    const int mt = blockIdx.x;
    const int h = blockIdx.y;
    const int kvh = h >> 2;                // repeat_interleave: head h -> kv head h/4
    const int m0 = mt * 64;
    const int tid = threadIdx.x;
    const int tx = tid & 15, ty = tid >> 4;

    for (int idx = tid; idx < 4096; idx += 256) {
        int kk = idx & 63, r = idx >> 6;
        Qt[kk * 64 + (r ^ (kk & 31))] = q[(size_t)(m0 + r) * C_DIM + h * HDIM + kk];
    }

    float o[4][4];
    float m_i[4], l_i[4];
#pragma unroll
    for (int i = 0; i < 4; i++) {
        m_i[i] = -1e30f; l_i[i] = 0.f;
#pragma unroll
        for (int j = 0; j < 4; j++) o[i][j] = 0.f;
    }

    const int nstart = (mt >= 8) ? (mt - 8) : 0;
    for (int nt = nstart; nt <= mt; nt++) {
        const int n0 = nt * 64;
        __syncthreads();  // prior-iter Ps/Vs reads done before overwrite
        for (int idx = tid; idx < 4096; idx += 256) {
            int kk = idx & 63, c = idx >> 6;
            KP[kk * 64 + (c ^ (kk & 31))] =
                kv[(size_t)(n0 + c) * KV_DIM + kvh * HDIM + kk];
        }
        for (int idx = tid; idx < 4096; idx += 256) {
            int c = idx & 63, k = idx >> 6;
            Vs[k * 64 + c] =
                kv[(size_t)(n0 + k) * KV_DIM + 256 + kvh * HDIM + c];
        }
        __syncthreads();

        // S = Q K^T
        float s[4][4];
#pragma unroll
        for (int i = 0; i < 4; i++)
#pragma unroll
            for (int j = 0; j < 4; j++) s[i][j] = 0.f;

#pragma unroll 4
        for (int kk = 0; kk < 64; kk++) {
            const int sw = kk & 31;
            float a[4], b[4];
#pragma unroll
            for (int i = 0; i < 4; i++) a[i] = Qt[kk * 64 + ((ty + 16 * i) ^ sw)];
#pragma unroll
            for (int j = 0; j < 4; j++) b[j] = KP[kk * 64 + ((tx + 16 * j) ^ sw)];
#pragma unroll
            for (int i = 0; i < 4; i++)
#pragma unroll
                for (int j = 0; j < 4; j++) s[i][j] += a[i] * b[j];
        }

        // scale + mask (only boundary tiles need it)
        const bool needmask = (nt == mt) || (nt == mt - 8);
#pragma unroll
        for (int i = 0; i < 4; i++)
#pragma unroll
            for (int j = 0; j < 4; j++) {
                float v = s[i][j] * 0.125f;  // 1/sqrt(64)
                if (needmask) {
                    int qr = m0 + ty + 16 * i;
                    int kc = n0 + tx + 16 * j;
                    if (kc > qr || kc <= qr - WINDOW_SZ) v = -1e30f;
                }
                s[i][j] = v;
            }

        // online softmax (row owned by 16 contiguous lanes: shfl width-16 reduce)
#pragma unroll
        for (int i = 0; i < 4; i++) {
            float tmax = fmaxf(fmaxf(s[i][0], s[i][1]), fmaxf(s[i][2], s[i][3]));
#pragma unroll
            for (int off = 8; off > 0; off >>= 1)
                tmax = fmaxf(tmax, __shfl_xor_sync(0xffffffffu, tmax, off));
            float mn = fmaxf(m_i[i], tmax);
            float corr = __expf(m_i[i] - mn);  // fully-masked history flushed: exp(-1e30-m)=0
            m_i[i] = mn;
            float rsum = 0.f;
#pragma unroll
            for (int j = 0; j < 4; j++) {
                float p = __expf(s[i][j] - mn);
                s[i][j] = p;
                rsum += p;
            }
#pragma unroll
            for (int off = 8; off > 0; off >>= 1)
                rsum += __shfl_xor_sync(0xffffffffu, rsum, off);
            l_i[i] = l_i[i] * corr + rsum;
#pragma unroll
            for (int j = 0; j < 4; j++) o[i][j] *= corr;
        }

        __syncthreads();  // Kt reads done -> overlay Ps
#pragma unroll
        for (int i = 0; i < 4; i++) {
            int r = ty + 16 * i;
#pragma unroll
            for (int j = 0; j < 4; j++)
                KP[r * 64 + ((tx + 16 * j) ^ (r & 31))] = s[i][j];
        }
        __syncthreads();

        // O += P @ V
#pragma unroll 4
        for (int k = 0; k < 64; k++) {
            float p[4], vv[4];
#pragma unroll
            for (int i = 0; i < 4; i++) {
                int r = ty + 16 * i;
                p[i] = KP[r * 64 + (k ^ (r & 31))];
            }
#pragma unroll
            for (int j = 0; j < 4; j++) vv[j] = Vs[k * 64 + tx + 16 * j];
#pragma unroll
            for (int i = 0; i < 4; i++)
#pragma unroll
                for (int j = 0; j < 4; j++) o[i][j] += p[i] * vv[j];
        }
    }

#pragma unroll
    for (int i = 0; i < 4; i++) {
        float inv = 1.f / l_i[i];
        int qr = m0 + ty + 16 * i;
#pragma unroll
        for (int j = 0; j < 4; j++)
            y[(size_t)qr * C_DIM + h * HDIM + tx + 16 * j] = o[i][j] * inv;
    }
}

// ---------------------------------------------------------------------------
extern "C" void kernel_launch(void* const* d_in, const int* in_sizes, int n_in,
                              void* d_out, int out_size)
{
    const float* x     = (const float*)d_in[0];
    const float* Wq    = (const float*)d_in[1];
    const float* Wkv   = (const float*)d_in[2];
    const float* Wproj = (const float*)d_in[3];
    float* out = (float*)d_out;

    float *gq, *gkv, *gy;
    cudaGetSymbolAddress((void**)&gq, g_q);
    cudaGetSymbolAddress((void**)&gkv, g_kv);
    cudaGetSymbolAddress((void**)&gy, g_y);

    // Q = x @ Wq^T  [2048,1024]
    gemm_tn<<<dim3(C_DIM / GBN, T_SEQ / GBM), 256>>>(x, Wq, gq, T_SEQ, C_DIM, C_DIM);
    // KV = x @ Wkv^T [2048,512]
    gemm_tn<<<dim3(KV_DIM / GBN, T_SEQ / GBM), 256>>>(x, Wkv, gkv, T_SEQ, KV_DIM, C_DIM);
    // L2 norm + RoPE on Q and K heads
    norm_rope_kernel<<<dim3(T_SEQ, HEADS + KV_HEADS), 32>>>(gq, gkv);
    // windowed attention -> y [2048,1024] (already in (T, H*d) layout)
    attn_kernel<<<dim3(T_SEQ / 64, HEADS), 256>>>(gq, gkv, gy);
    // out = y @ Wproj^T
    gemm_tn<<<dim3(C_DIM / GBN, T_SEQ / GBM), 256>>>(gy, Wproj, out, T_SEQ, C_DIM, C_DIM);
}

// round 8
// speedup vs baseline: 1.4167x; 1.4167x over previous
#include <cuda_runtime.h>
#include <math.h>

#define T_SEQ 2048
#define C_DIM 1024
#define HEADS 16
#define KV_HEADS 4
#define HDIM 64
#define KV_DIM 512
#define WINDOW_SZ 512

// Scratch (no cudaMalloc allowed)
__device__ float g_q[T_SEQ * C_DIM];    // 8 MB
__device__ float g_kv[T_SEQ * KV_DIM];  // 4 MB  (K: cols 0..255, V: cols 256..511)
__device__ float g_y[T_SEQ * C_DIM];    // 8 MB

// ---------------------------------------------------------------------------
// GEMM: C[M,N] = A[M,K] * B[N,K]^T  (both K-major). 128x128x8 tile, 256 thr,
// 8x8 microtile, double-buffered smem with register prefetch (1 sync/iter).
// ---------------------------------------------------------------------------
#define GBM 128
#define GBN 128
#define GBK 8
#define GST 132

__global__ __launch_bounds__(256, 2)
void gemm_tn(const float* __restrict__ A, const float* __restrict__ B,
             float* __restrict__ C, int M, int N, int K)
{
    __shared__ float As[2][GBK * GST];
    __shared__ float Bs[2][GBK * GST];
    const int tid = threadIdx.x;
    const int tx = tid & 15, ty = tid >> 4;
    const int m0 = blockIdx.y * GBM, n0 = blockIdx.x * GBN;
    const int lrow = tid >> 1, lcol = (tid & 1) * 4;

    const float* Ap = A + (size_t)(m0 + lrow) * K + lcol;
    const float* Bp = B + (size_t)(n0 + lrow) * K + lcol;

    float4 av = *reinterpret_cast<const float4*>(Ap);
    float4 bv = *reinterpret_cast<const float4*>(Bp);
    As[0][(lcol + 0) * GST + lrow] = av.x;
    As[0][(lcol + 1) * GST + lrow] = av.y;
    As[0][(lcol + 2) * GST + lrow] = av.z;
    As[0][(lcol + 3) * GST + lrow] = av.w;
    Bs[0][(lcol + 0) * GST + lrow] = bv.x;
    Bs[0][(lcol + 1) * GST + lrow] = bv.y;
    Bs[0][(lcol + 2) * GST + lrow] = bv.z;
    Bs[0][(lcol + 3) * GST + lrow] = bv.w;
    __syncthreads();

    float acc[8][8];
#pragma unroll
    for (int i = 0; i < 8; i++)
#pragma unroll
        for (int j = 0; j < 8; j++) acc[i][j] = 0.f;

    int buf = 0;
    for (int k0 = 0; k0 < K; k0 += GBK) {
        const bool hn = (k0 + GBK) < K;
        if (hn) {
            av = *reinterpret_cast<const float4*>(Ap + k0 + GBK);
            bv = *reinterpret_cast<const float4*>(Bp + k0 + GBK);
        }
#pragma unroll
        for (int kk = 0; kk < GBK; kk++) {
            float a[8], b[8];
            float4 t0 = *reinterpret_cast<const float4*>(&As[buf][kk * GST + 4 * ty]);
            float4 t1 = *reinterpret_cast<const float4*>(&As[buf][kk * GST + 4 * ty + 64]);
            float4 t2 = *reinterpret_cast<const float4*>(&Bs[buf][kk * GST + 4 * tx]);
            float4 t3 = *reinterpret_cast<const float4*>(&Bs[buf][kk * GST + 4 * tx + 64]);
            a[0] = t0.x; a[1] = t0.y; a[2] = t0.z; a[3] = t0.w;
            a[4] = t1.x; a[5] = t1.y; a[6] = t1.z; a[7] = t1.w;
            b[0] = t2.x; b[1] = t2.y; b[2] = t2.z; b[3] = t2.w;
            b[4] = t3.x; b[5] = t3.y; b[6] = t3.z; b[7] = t3.w;
#pragma unroll
            for (int i = 0; i < 8; i++)
#pragma unroll
                for (int j = 0; j < 8; j++) acc[i][j] += a[i] * b[j];
        }
        if (hn) {
            const int nb = buf ^ 1;
            As[nb][(lcol + 0) * GST + lrow] = av.x;
            As[nb][(lcol + 1) * GST + lrow] = av.y;
            As[nb][(lcol + 2) * GST + lrow] = av.z;
            As[nb][(lcol + 3) * GST + lrow] = av.w;
            Bs[nb][(lcol + 0) * GST + lrow] = bv.x;
            Bs[nb][(lcol + 1) * GST + lrow] = bv.y;
            Bs[nb][(lcol + 2) * GST + lrow] = bv.z;
            Bs[nb][(lcol + 3) * GST + lrow] = bv.w;
            __syncthreads();
            buf = nb;
        }
    }

#pragma unroll
    for (int i = 0; i < 8; i++) {
        int r = m0 + 4 * ty + (i & 3) + ((i >= 4) ? 64 : 0);
        float4 w0 = make_float4(acc[i][0], acc[i][1], acc[i][2], acc[i][3]);
        float4 w1 = make_float4(acc[i][4], acc[i][5], acc[i][6], acc[i][7]);
        *reinterpret_cast<float4*>(&C[(size_t)r * N + n0 + 4 * tx]) = w0;
        *reinterpret_cast<float4*>(&C[(size_t)r * N + n0 + 64 + 4 * tx]) = w1;
    }
}

// ---------------------------------------------------------------------------
// QK L2-normalize + RoPE. One warp per (t, head).
// ---------------------------------------------------------------------------
__global__ void norm_rope_kernel(float* __restrict__ q, float* __restrict__ kvbuf)
{
    const int t = blockIdx.x;
    const int h = blockIdx.y;
    const int lane = threadIdx.x;
    float* base = (h < HEADS)
        ? q + (size_t)t * C_DIM + h * HDIM
        : kvbuf + (size_t)t * KV_DIM + (h - HEADS) * HDIM;

    float a = base[lane];
    float b = base[lane + 32];
    float ss = a * a + b * b;
#pragma unroll
    for (int off = 16; off > 0; off >>= 1)
        ss += __shfl_xor_sync(0xffffffffu, ss, off);
    float inv = 1.f / (sqrtf(ss) + 1e-6f);

    float theta = powf(10000.f, -(float)lane * (1.f / 32.f));
    float ang = (float)t * theta;
    float sv, cv;
    sincosf(ang, &sv, &cv);

    base[lane]      = (a * cv - b * sv) * inv;
    base[lane + 32] = (b * cv + a * sv) * inv;
}

// ---------------------------------------------------------------------------
// Windowed flash attention v2.
// 128 threads, 64 q-rows x 64-key tiles, 4x8 microtile.
// ty=tid>>3 -> rows 4ty..4ty+3 ; tx=tid&7 -> cols 8tx..8tx+7.
// Qt/Kt: [kk][r] stride 64, all compute reads are LDS.128, affine addresses.
// P tile overlays Kt with float4-granular XOR swizzle (chunk = ty ^ ((k>>2)&15))
// -> conflict-free broadcast reads in PV, one XOR per 4 iterations.
// ---------------------------------------------------------------------------
__global__ __launch_bounds__(128, 4)
void attn_kernel(const float* __restrict__ q, const float* __restrict__ kv,
                 float* __restrict__ y)
{
    __shared__ float Qt[64 * 64];  // [kk][r]
    __shared__ float KP[64 * 64];  // Kt: [kk][c]; later P: [k][r] chunk-swizzled
    __shared__ float Vs[64 * 64];  // [k][c]

    const int mt = blockIdx.x;
    const int h = blockIdx.y;
    const int kvh = h >> 2;
    const int m0 = mt * 64;
    const int tid = threadIdx.x;
    const int tx = tid & 7, ty = tid >> 3;

    // load Q tile transposed: warp = 32 consecutive r, fixed kk-chunk ->
    // conflict-free scalar smem stores.
#pragma unroll
    for (int it = 0; it < 8; it++) {
        int idx = tid + it * 128;
        int r = idx & 63, kc = idx >> 6;
        float4 v = *reinterpret_cast<const float4*>(
            &q[(size_t)(m0 + r) * C_DIM + h * HDIM + kc * 4]);
        Qt[(kc * 4 + 0) * 64 + r] = v.x;
        Qt[(kc * 4 + 1) * 64 + r] = v.y;
        Qt[(kc * 4 + 2) * 64 + r] = v.z;
        Qt[(kc * 4 + 3) * 64 + r] = v.w;
    }

    float o[4][8];
    float m_i[4], l_i[4];
#pragma unroll
    for (int i = 0; i < 4; i++) {
        m_i[i] = -1e30f; l_i[i] = 0.f;
#pragma unroll
        for (int j = 0; j < 8; j++) o[i][j] = 0.f;
    }

    const int nstart = (mt >= 8) ? (mt - 8) : 0;
    for (int nt = nstart; nt <= mt; nt++) {
        const int n0 = nt * 64;
        __syncthreads();  // prior-iter P/V reads done before overwrite

        // K tile transposed
#pragma unroll
        for (int it = 0; it < 8; it++) {
            int idx = tid + it * 128;
            int c = idx & 63, kc = idx >> 6;
            float4 v = *reinterpret_cast<const float4*>(
                &kv[(size_t)(n0 + c) * KV_DIM + kvh * HDIM + kc * 4]);
            KP[(kc * 4 + 0) * 64 + c] = v.x;
            KP[(kc * 4 + 1) * 64 + c] = v.y;
            KP[(kc * 4 + 2) * 64 + c] = v.z;
            KP[(kc * 4 + 3) * 64 + c] = v.w;
        }
        // V tile natural layout (coalesced)
#pragma unroll
        for (int it = 0; it < 8; it++) {
            int idx = tid + it * 128;
            int k = idx >> 4, c4 = (idx & 15) * 4;
            *reinterpret_cast<float4*>(&Vs[k * 64 + c4]) =
                *reinterpret_cast<const float4*>(
                    &kv[(size_t)(n0 + k) * KV_DIM + 256 + kvh * HDIM + c4]);
        }
        __syncthreads();

        // S = Q K^T : per kk, 3x LDS.128 + 32 FMA
        float s[4][8];
#pragma unroll
        for (int i = 0; i < 4; i++)
#pragma unroll
            for (int j = 0; j < 8; j++) s[i][j] = 0.f;

        const float* qp = Qt + 4 * ty;
        const float* kp = KP + 8 * tx;
#pragma unroll 8
        for (int kk = 0; kk < 64; kk++) {
            float4 a4 = *reinterpret_cast<const float4*>(qp + kk * 64);
            float4 b0 = *reinterpret_cast<const float4*>(kp + kk * 64);
            float4 b1 = *reinterpret_cast<const float4*>(kp + kk * 64 + 4);
            float a[4] = {a4.x, a4.y, a4.z, a4.w};
            float b[8] = {b0.x, b0.y, b0.z, b0.w, b1.x, b1.y, b1.z, b1.w};
#pragma unroll
            for (int i = 0; i < 4; i++)
#pragma unroll
                for (int j = 0; j < 8; j++) s[i][j] += a[i] * b[j];
        }

        // scale + mask (boundary tiles only)
        const bool needmask = (nt == mt) || (nt == mt - 8);
#pragma unroll
        for (int i = 0; i < 4; i++)
#pragma unroll
            for (int j = 0; j < 8; j++) {
                float v = s[i][j] * 0.125f;  // 1/sqrt(64)
                if (needmask) {
                    int qr = m0 + 4 * ty + i;
                    int kc = n0 + 8 * tx + j;
                    if (kc > qr || kc <= qr - WINDOW_SZ) v = -1e30f;
                }
                s[i][j] = v;
            }

        // online softmax; row owned by 8 consecutive lanes (same ty)
#pragma unroll
        for (int i = 0; i < 4; i++) {
            float tmax = s[i][0];
#pragma unroll
            for (int j = 1; j < 8; j++) tmax = fmaxf(tmax, s[i][j]);
#pragma unroll
            for (int off = 4; off > 0; off >>= 1)
                tmax = fmaxf(tmax, __shfl_xor_sync(0xffffffffu, tmax, off));
            float mn = fmaxf(m_i[i], tmax);
            float corr = __expf(m_i[i] - mn);
            m_i[i] = mn;
            float rsum = 0.f;
#pragma unroll
            for (int j = 0; j < 8; j++) {
                float p = __expf(s[i][j] - mn);
                s[i][j] = p;
                rsum += p;
            }
#pragma unroll
            for (int off = 4; off > 0; off >>= 1)
                rsum += __shfl_xor_sync(0xffffffffu, rsum, off);
            l_i[i] = l_i[i] * corr + rsum;
#pragma unroll
            for (int j = 0; j < 8; j++) o[i][j] *= corr;
        }

        __syncthreads();  // all QK reads of KP done -> overlay P
        // store P as [k][r], float4 chunks swizzled: chunk = ty ^ ((k>>2)&15)
#pragma unroll
        for (int j = 0; j < 8; j++) {
            int k = 8 * tx + j;
            int ch = ty ^ ((k >> 2) & 15);
            *reinterpret_cast<float4*>(&KP[k * 64 + 4 * ch]) =
                make_float4(s[0][j], s[1][j], s[2][j], s[3][j]);
        }
        __syncthreads();

        // O += P @ V : per k, 3x LDS.128 + 32 FMA
#pragma unroll 8
        for (int k = 0; k < 64; k++) {
            float4 p4 = *reinterpret_cast<const float4*>(
                &KP[k * 64 + 4 * (ty ^ ((k >> 2) & 15))]);
            float4 v0 = *reinterpret_cast<const float4*>(&Vs[k * 64 + 8 * tx]);
            float4 v1 = *reinterpret_cast<const float4*>(&Vs[k * 64 + 8 * tx + 4]);
            float p[4] = {p4.x, p4.y, p4.z, p4.w};
            float vv[8] = {v0.x, v0.y, v0.z, v0.w, v1.x, v1.y, v1.z, v1.w};
#pragma unroll
            for (int i = 0; i < 4; i++)
#pragma unroll
                for (int j = 0; j < 8; j++) o[i][j] += p[i] * vv[j];
        }
    }

#pragma unroll
    for (int i = 0; i < 4; i++) {
        float inv = 1.f / l_i[i];
        int qr = m0 + 4 * ty + i;
        float4 w0 = make_float4(o[i][0] * inv, o[i][1] * inv, o[i][2] * inv, o[i][3] * inv);
        float4 w1 = make_float4(o[i][4] * inv, o[i][5] * inv, o[i][6] * inv, o[i][7] * inv);
        *reinterpret_cast<float4*>(&y[(size_t)qr * C_DIM + h * HDIM + 8 * tx]) = w0;
        *reinterpret_cast<float4*>(&y[(size_t)qr * C_DIM + h * HDIM + 8 * tx + 4]) = w1;
    }
}

// ---------------------------------------------------------------------------
extern "C" void kernel_launch(void* const* d_in, const int* in_sizes, int n_in,
                              void* d_out, int out_size)
{
    const float* x     = (const float*)d_in[0];
    const float* Wq    = (const float*)d_in[1];
    const float* Wkv   = (const float*)d_in[2];
    const float* Wproj = (const float*)d_in[3];
    float* out = (float*)d_out;

    float *gq, *gkv, *gy;
    cudaGetSymbolAddress((void**)&gq, g_q);
    cudaGetSymbolAddress((void**)&gkv, g_kv);
    cudaGetSymbolAddress((void**)&gy, g_y);

    gemm_tn<<<dim3(C_DIM / GBN, T_SEQ / GBM), 256>>>(x, Wq, gq, T_SEQ, C_DIM, C_DIM);
    gemm_tn<<<dim3(KV_DIM / GBN, T_SEQ / GBM), 256>>>(x, Wkv, gkv, T_SEQ, KV_DIM, C_DIM);
    norm_rope_kernel<<<dim3(T_SEQ, HEADS + KV_HEADS), 32>>>(gq, gkv);
    attn_kernel<<<dim3(T_SEQ / 64, HEADS), 128>>>(gq, gkv, gy);
    gemm_tn<<<dim3(C_DIM / GBN, T_SEQ / GBM), 256>>>(gy, Wproj, out, T_SEQ, C_DIM, C_DIM);
}